// round 4
// baseline (speedup 1.0000x reference)
#include <cuda_runtime.h>

#define N_ATOMS 10000
#define N_PAIRS 500000
#define N_DESC  64
#define N_GROUPS (N_PAIRS / 2)           // 2 pairs per group (16-lane halves)

#define TABLE_TPB 256
#define TABLE_BLOCKS ((N_ATOMS * N_DESC + TABLE_TPB - 1) / TABLE_TPB)   // 2500

#define PAIR_BLOCKS 1184                 // 148 SMs * 8 CTAs -> one wave
#define PAIR_TPB    256
#define PAIR_WARPS  (PAIR_BLOCKS * PAIR_TPB / 32)   // 9472

// Precomputed per-atom table: g[n,d] = (1 - tanh^2(coeffs*w1+b1)) * w1[d] * w_last[d]
__device__ float g_table[N_ATOMS * N_DESC];
// Per-block energy partials from the table kernel
__device__ float e_partials[TABLE_BLOCKS];

// ---------------------------------------------------------------------------
// Kernel 1: build g table, zero forces, write per-block energy partials.
// One thread per (atom, descriptor).
// ---------------------------------------------------------------------------
__global__ void table_energy_kernel(const float* __restrict__ coeffs,
                                    const float* __restrict__ w1,
                                    const float* __restrict__ b1,
                                    const float* __restrict__ w_last,
                                    float* __restrict__ out_f) {   // out+1
    int idx = blockIdx.x * blockDim.x + threadIdx.x;
    float e_contrib = 0.0f;
    if (idx < N_ATOMS * N_DESC) {
        int d = idx & (N_DESC - 1);
        float w = w1[d];
        float wl = w_last[d];
        float e = tanhf(fmaf(coeffs[idx], w, b1[d]));
        g_table[idx] = (1.0f - e * e) * w * wl;
        e_contrib = e * wl;
    }
    // zero the force output (3*N_ATOMS = 30000 floats)
    if (idx < 3 * N_ATOMS) out_f[idx] = 0.0f;

    // block reduction of energy contribution
    __shared__ float red[TABLE_TPB / 32];
    #pragma unroll
    for (int o = 16; o > 0; o >>= 1)
        e_contrib += __shfl_xor_sync(0xFFFFFFFFu, e_contrib, o);
    int lane = threadIdx.x & 31;
    int wid = threadIdx.x >> 5;
    if (lane == 0) red[wid] = e_contrib;
    __syncthreads();
    if (wid == 0) {
        float v = (lane < (TABLE_TPB >> 5)) ? red[lane] : 0.0f;
        #pragma unroll
        for (int o = 16; o > 0; o >>= 1)
            v += __shfl_xor_sync(0xFFFFFFFFu, v, o);
        if (lane == 0) e_partials[blockIdx.x] = v;
    }
}

// ---------------------------------------------------------------------------
// Kernel 2: pair contraction + scatter, persistent one-wave grid.
// Warp handles 2 consecutive GROUPS (= 4 consecutive pairs) per iteration:
// 6 independent float4 deriv loads + 2 g-gathers in flight per thread.
// lanes 0-15 -> even pair of each group, lanes 16-31 -> odd pair.
// One designated warp (block 0, warp 0) also finalizes the energy.
// ---------------------------------------------------------------------------
__global__ void __launch_bounds__(PAIR_TPB, 6) pair_kernel(
    const float* __restrict__ derivs,          // [3, N_PAIRS, 64]
    const int* __restrict__ central,
    const int* __restrict__ neigh,
    const float* __restrict__ b_last,
    float* __restrict__ out)                   // [0]=energy, [1..]=forces [3,N_ATOMS]
{
    const unsigned lane = threadIdx.x & 31;
    const unsigned half = lane >> 4;
    const unsigned l16  = lane & 15;
    const unsigned warp = (blockIdx.x * PAIR_TPB + threadIdx.x) >> 5;
    const size_t ds = (size_t)N_PAIRS * N_DESC;
    float* out_f = out + 1;

    // ---- energy finalize (one warp; table kernel already completed) ----
    if (blockIdx.x == 0 && (threadIdx.x >> 5) == 0) {
        float v = 0.0f;
        for (int i = lane; i < TABLE_BLOCKS; i += 32) v += e_partials[i];
        #pragma unroll
        for (int o = 16; o > 0; o >>= 1)
            v += __shfl_xor_sync(0xFFFFFFFFu, v, o);
        if (lane == 0) out[0] = v * (1.0f / (float)N_ATOMS) + b_last[0];
    }

    // ---- pair loop: 2 groups per iteration ----
    // warp w starts at group 2*w, strides by 2*PAIR_WARPS.
    // N_GROUPS (250000) is even and start is even, so g0+1 is always valid
    // whenever g0 < N_GROUPS.
    for (unsigned g0 = warp * 2; g0 < N_GROUPS; g0 += 2 * PAIR_WARPS) {
        unsigned pA = g0 * 2 + half;       // pair in group g0
        unsigned pB = pA + 2;              // pair in group g0+1

        int cA  = __ldg(central + pA);
        int nbA = __ldg(neigh + pA);
        int cB  = __ldg(central + pB);
        int nbB = __ldg(neigh + pB);

        float4 gA = *(const float4*)(g_table + (size_t)cA * N_DESC + l16 * 4);
        float4 gB = *(const float4*)(g_table + (size_t)cB * N_DESC + l16 * 4);

        const float* baseA = derivs + (size_t)pA * N_DESC + l16 * 4;
        const float* baseB = derivs + (size_t)pB * N_DESC + l16 * 4;
        float4 a0 = __ldcs((const float4*)(baseA));
        float4 a1 = __ldcs((const float4*)(baseA + ds));
        float4 a2 = __ldcs((const float4*)(baseA + 2 * ds));
        float4 b0 = __ldcs((const float4*)(baseB));
        float4 b1v = __ldcs((const float4*)(baseB + ds));
        float4 b2 = __ldcs((const float4*)(baseB + 2 * ds));

        float sA0 = fmaf(a0.x, gA.x, fmaf(a0.y, gA.y, fmaf(a0.z, gA.z, a0.w * gA.w)));
        float sA1 = fmaf(a1.x, gA.x, fmaf(a1.y, gA.y, fmaf(a1.z, gA.z, a1.w * gA.w)));
        float sA2 = fmaf(a2.x, gA.x, fmaf(a2.y, gA.y, fmaf(a2.z, gA.z, a2.w * gA.w)));
        float sB0 = fmaf(b0.x, gB.x, fmaf(b0.y, gB.y, fmaf(b0.z, gB.z, b0.w * gB.w)));
        float sB1 = fmaf(b1v.x, gB.x, fmaf(b1v.y, gB.y, fmaf(b1v.z, gB.z, b1v.w * gB.w)));
        float sB2 = fmaf(b2.x, gB.x, fmaf(b2.y, gB.y, fmaf(b2.z, gB.z, b2.w * gB.w)));

        #pragma unroll
        for (int o = 8; o > 0; o >>= 1) {
            sA0 += __shfl_xor_sync(0xFFFFFFFFu, sA0, o);
            sA1 += __shfl_xor_sync(0xFFFFFFFFu, sA1, o);
            sA2 += __shfl_xor_sync(0xFFFFFFFFu, sA2, o);
            sB0 += __shfl_xor_sync(0xFFFFFFFFu, sB0, o);
            sB1 += __shfl_xor_sync(0xFFFFFFFFu, sB1, o);
            sB2 += __shfl_xor_sync(0xFFFFFFFFu, sB2, o);
        }

        if (l16 < 3) {
            float sA = (l16 == 0) ? sA0 : (l16 == 1) ? sA1 : sA2;
            float sB = (l16 == 0) ? sB0 : (l16 == 1) ? sB1 : sB2;
            atomicAdd(out_f + (size_t)l16 * N_ATOMS + nbA, -sA);
            atomicAdd(out_f + (size_t)l16 * N_ATOMS + nbB, -sB);
        }
    }
}

// ---------------------------------------------------------------------------
extern "C" void kernel_launch(void* const* d_in, const int* in_sizes, int n_in,
                              void* d_out, int out_size) {
    const float* coeffs   = (const float*)d_in[0];   // [1, N_ATOMS, 64]
    const float* derivs   = (const float*)d_in[1];   // [1, 3, N_PAIRS, 64]
    const float* w1       = (const float*)d_in[2];
    const float* b1       = (const float*)d_in[3];
    const float* w_last   = (const float*)d_in[4];
    const float* b_last   = (const float*)d_in[5];
    const int*   central  = (const int*)d_in[6];
    const int*   neigh    = (const int*)d_in[7];
    float* out = (float*)d_out;                      // [0]=energy, [1..30000]=forces [3,N_ATOMS]

    // 1) g table + energy partials + force zeroing (single launch)
    table_energy_kernel<<<TABLE_BLOCKS, TABLE_TPB>>>(coeffs, w1, b1, w_last, out + 1);

    // 2) pair contraction + scatter + energy finalize (persistent, one wave)
    pair_kernel<<<PAIR_BLOCKS, PAIR_TPB>>>(derivs, central, neigh, b_last, out);
}

// round 5
// speedup vs baseline: 1.0288x; 1.0288x over previous
#include <cuda_runtime.h>

#define N_ATOMS 10000
#define N_PAIRS 500000
#define N_DESC  64
#define N_GROUPS (N_PAIRS / 2)           // 2 pairs per warp-iteration

#define TABLE_TPB 256
#define TABLE_BLOCKS ((N_ATOMS * N_DESC + TABLE_TPB - 1) / TABLE_TPB)   // 2500

#define PAIR_BLOCKS 1184                 // 148 SMs * 8 CTAs -> one wave
#define PAIR_TPB    256
#define PAIR_WARPS  (PAIR_BLOCKS * PAIR_TPB / 32)   // 9472

// Precomputed per-atom table: g[n,d] = (1 - tanh^2(coeffs*w1+b1)) * w1[d] * w_last[d]
__device__ float g_table[N_ATOMS * N_DESC];
// Per-block energy partials from the table kernel
__device__ float e_partials[TABLE_BLOCKS];

// ---------------------------------------------------------------------------
// Kernel 1: build g table, zero forces, write per-block energy partials.
// One thread per (atom, descriptor).
// ---------------------------------------------------------------------------
__global__ void table_energy_kernel(const float* __restrict__ coeffs,
                                    const float* __restrict__ w1,
                                    const float* __restrict__ b1,
                                    const float* __restrict__ w_last,
                                    float* __restrict__ out_f) {   // out+1
    int idx = blockIdx.x * blockDim.x + threadIdx.x;
    float e_contrib = 0.0f;
    if (idx < N_ATOMS * N_DESC) {
        int d = idx & (N_DESC - 1);
        float w = w1[d];
        float wl = w_last[d];
        float e = tanhf(fmaf(coeffs[idx], w, b1[d]));
        g_table[idx] = (1.0f - e * e) * w * wl;
        e_contrib = e * wl;
    }
    // zero the force output (3*N_ATOMS = 30000 floats)
    if (idx < 3 * N_ATOMS) out_f[idx] = 0.0f;

    // block reduction of energy contribution
    __shared__ float red[TABLE_TPB / 32];
    #pragma unroll
    for (int o = 16; o > 0; o >>= 1)
        e_contrib += __shfl_xor_sync(0xFFFFFFFFu, e_contrib, o);
    int lane = threadIdx.x & 31;
    int wid = threadIdx.x >> 5;
    if (lane == 0) red[wid] = e_contrib;
    __syncthreads();
    if (wid == 0) {
        float v = (lane < (TABLE_TPB >> 5)) ? red[lane] : 0.0f;
        #pragma unroll
        for (int o = 16; o > 0; o >>= 1)
            v += __shfl_xor_sync(0xFFFFFFFFu, v, o);
        if (lane == 0) e_partials[blockIdx.x] = v;
    }
}

// ---------------------------------------------------------------------------
// Kernel 2: pair contraction + scatter. PERSISTENT (one wave), grid-stride
// over pair-groups. Two pairs per warp-iteration: lanes 0-15 -> pair 2g,
// lanes 16-31 -> pair 2g+1. Each lane owns 4 descriptors (float4): each
// deriv load is one warp-wide contiguous 512 B LDG.128. Derivs use __ldcs
// (evict-first) so L2 keeps g_table + the force accumulator resident.
// Next iteration's indices are prefetched before the current reduction.
// Warp 0 of block 0 additionally finalizes the energy from the partials.
// ---------------------------------------------------------------------------
__global__ void __launch_bounds__(PAIR_TPB, 8) pair_kernel(
    const float* __restrict__ derivs,          // [3, N_PAIRS, 64]
    const int* __restrict__ central,
    const int* __restrict__ neigh,
    const float* __restrict__ b_last,
    float* __restrict__ out)                   // [0]=energy, [1..]=forces [3,N_ATOMS]
{
    const unsigned lane = threadIdx.x & 31;
    const unsigned half = lane >> 4;           // which pair of the group
    const unsigned l16  = lane & 15;
    const unsigned warp0 = (blockIdx.x * PAIR_TPB + threadIdx.x) >> 5;
    const size_t ds = (size_t)N_PAIRS * N_DESC;
    float* out_f = out + 1;

    // ---- energy finalize (one warp; table kernel already completed) ----
    if (blockIdx.x == 0 && (threadIdx.x >> 5) == 0) {
        float v = 0.0f;
        for (int i = lane; i < TABLE_BLOCKS; i += 32) v += e_partials[i];
        #pragma unroll
        for (int o = 16; o > 0; o >>= 1)
            v += __shfl_xor_sync(0xFFFFFFFFu, v, o);
        if (lane == 0) out[0] = v * (1.0f / (float)N_ATOMS) + b_last[0];
    }

    unsigned pg = warp0;
    if (pg >= N_GROUPS) return;

    unsigned p = pg * 2 + half;
    int c  = __ldg(central + p);
    int nb = __ldg(neigh + p);

    while (true) {
        // gather g row (L2-resident), 4 descriptors per lane
        float4 g = *(const float4*)(g_table + (size_t)c * N_DESC + l16 * 4);

        const float* base = derivs + (size_t)p * N_DESC + l16 * 4;
        float4 v0 = __ldcs((const float4*)(base));
        float4 v1 = __ldcs((const float4*)(base + ds));
        float4 v2 = __ldcs((const float4*)(base + 2 * ds));

        // prefetch next group's indices (overlaps with reduction below)
        unsigned pg_next = pg + PAIR_WARPS;
        bool more = (pg_next < N_GROUPS);
        int c2 = 0, nb2 = 0;
        unsigned p_next = pg_next * 2 + half;
        if (more) {
            c2  = __ldg(central + p_next);
            nb2 = __ldg(neigh + p_next);
        }

        float s0 = fmaf(v0.x, g.x, fmaf(v0.y, g.y, fmaf(v0.z, g.z, v0.w * g.w)));
        float s1 = fmaf(v1.x, g.x, fmaf(v1.y, g.y, fmaf(v1.z, g.z, v1.w * g.w)));
        float s2 = fmaf(v2.x, g.x, fmaf(v2.y, g.y, fmaf(v2.z, g.z, v2.w * g.w)));

        // reduce within each 16-lane half
        #pragma unroll
        for (int o = 8; o > 0; o >>= 1) {
            s0 += __shfl_xor_sync(0xFFFFFFFFu, s0, o);
            s1 += __shfl_xor_sync(0xFFFFFFFFu, s1, o);
            s2 += __shfl_xor_sync(0xFFFFFFFFu, s2, o);
        }

        if (l16 < 3) {
            float s = (l16 == 0) ? s0 : (l16 == 1) ? s1 : s2;
            atomicAdd(out_f + (size_t)l16 * N_ATOMS + nb, -s);
        }

        if (!more) break;
        pg = pg_next;
        p  = p_next;
        c  = c2;
        nb = nb2;
    }
}

// ---------------------------------------------------------------------------
extern "C" void kernel_launch(void* const* d_in, const int* in_sizes, int n_in,
                              void* d_out, int out_size) {
    const float* coeffs   = (const float*)d_in[0];   // [1, N_ATOMS, 64]
    const float* derivs   = (const float*)d_in[1];   // [1, 3, N_PAIRS, 64]
    const float* w1       = (const float*)d_in[2];
    const float* b1       = (const float*)d_in[3];
    const float* w_last   = (const float*)d_in[4];
    const float* b_last   = (const float*)d_in[5];
    const int*   central  = (const int*)d_in[6];
    const int*   neigh    = (const int*)d_in[7];
    float* out = (float*)d_out;                      // [0]=energy, [1..30000]=forces [3,N_ATOMS]

    // 1) g table + energy partials + force zeroing (single launch, no memset)
    table_energy_kernel<<<TABLE_BLOCKS, TABLE_TPB>>>(coeffs, w1, b1, w_last, out + 1);

    // 2) pair contraction + scatter + energy finalize (persistent, one wave)
    pair_kernel<<<PAIR_BLOCKS, PAIR_TPB>>>(derivs, central, neigh, b_last, out);
}

// round 6
// speedup vs baseline: 1.1579x; 1.1255x over previous
#include <cuda_runtime.h>

#define N_ATOMS 10000
#define N_PAIRS 500000
#define N_DESC  64

#define TABLE_TPB 256
#define TABLE_BLOCKS ((N_ATOMS * N_DESC / 4 + TABLE_TPB - 1) / TABLE_TPB)   // 625

// Precomputed per-atom table: g[n,d] = (1 - tanh^2(coeffs*w1+b1)) * w1[d] * w_last[d]
__device__ float g_table[N_ATOMS * N_DESC];
// Per-block energy partials from the table kernel
__device__ float e_partials[TABLE_BLOCKS];

// ---------------------------------------------------------------------------
// Kernel 1: build g table (float4-vectorized), zero forces, write per-block
// energy partials. One thread per 4 (atom,descriptor) elements.
// ---------------------------------------------------------------------------
__global__ void table_energy_kernel(const float4* __restrict__ coeffs4,
                                    const float4* __restrict__ w1_4,
                                    const float4* __restrict__ b1_4,
                                    const float4* __restrict__ wl_4,
                                    float* __restrict__ out_f) {   // out+1
    int idx = blockIdx.x * blockDim.x + threadIdx.x;   // over 160000 float4s
    float e_contrib = 0.0f;
    if (idx < N_ATOMS * N_DESC / 4) {
        int d4 = idx & (N_DESC / 4 - 1);               // descriptor group 0..15
        float4 w  = w1_4[d4];
        float4 b  = b1_4[d4];
        float4 wl = wl_4[d4];
        float4 c  = coeffs4[idx];
        float ex = tanhf(fmaf(c.x, w.x, b.x));
        float ey = tanhf(fmaf(c.y, w.y, b.y));
        float ez = tanhf(fmaf(c.z, w.z, b.z));
        float ew = tanhf(fmaf(c.w, w.w, b.w));
        float4 g;
        g.x = (1.0f - ex * ex) * w.x * wl.x;
        g.y = (1.0f - ey * ey) * w.y * wl.y;
        g.z = (1.0f - ez * ez) * w.z * wl.z;
        g.w = (1.0f - ew * ew) * w.w * wl.w;
        *(float4*)(g_table + idx * 4) = g;
        e_contrib = fmaf(ex, wl.x, fmaf(ey, wl.y, fmaf(ez, wl.z, ew * wl.w)));
    }
    // zero the force output (3*N_ATOMS = 30000 floats; out_f only 4B-aligned)
    if (idx < 3 * N_ATOMS) out_f[idx] = 0.0f;

    // block reduction of energy contribution
    __shared__ float red[TABLE_TPB / 32];
    #pragma unroll
    for (int o = 16; o > 0; o >>= 1)
        e_contrib += __shfl_xor_sync(0xFFFFFFFFu, e_contrib, o);
    int lane = threadIdx.x & 31;
    int wid = threadIdx.x >> 5;
    if (lane == 0) red[wid] = e_contrib;
    __syncthreads();
    if (wid == 0) {
        float v = (lane < (TABLE_TPB >> 5)) ? red[lane] : 0.0f;
        #pragma unroll
        for (int o = 16; o > 0; o >>= 1)
            v += __shfl_xor_sync(0xFFFFFFFFu, v, o);
        if (lane == 0) e_partials[blockIdx.x] = v;
    }
}

// ---------------------------------------------------------------------------
// Kernel 2: pair contraction + scatter. Non-persistent (wall-clock best):
// TWO pairs per warp, lanes 0-15 -> pair 2w, lanes 16-31 -> pair 2w+1.
// Each lane owns 4 descriptors (float4); each deriv load is one warp-wide
// contiguous 512 B LDG.128. Derivs use __ldcs (evict-first) so L2 keeps
// g_table + the force accumulator resident.
// Block 0 / warp 0 additionally finalizes the energy from the partials.
// Grid covers exactly N_PAIRS/2 warps — no bounds check needed.
// ---------------------------------------------------------------------------
__global__ void __launch_bounds__(256) pair_kernel(
    const float* __restrict__ derivs,          // [3, N_PAIRS, 64]
    const int* __restrict__ central,
    const int* __restrict__ neigh,
    const float* __restrict__ b_last,
    float* __restrict__ out)                   // [0]=energy, [1..]=forces [3,N_ATOMS]
{
    const unsigned lane = threadIdx.x & 31;
    float* out_f = out + 1;

    // ---- energy finalize (one warp; table kernel already completed) ----
    if (blockIdx.x == 0 && (threadIdx.x >> 5) == 0) {
        float v = 0.0f;
        for (int i = lane; i < TABLE_BLOCKS; i += 32) v += e_partials[i];
        #pragma unroll
        for (int o = 16; o > 0; o >>= 1)
            v += __shfl_xor_sync(0xFFFFFFFFu, v, o);
        if (lane == 0) out[0] = v * (1.0f / (float)N_ATOMS) + b_last[0];
    }

    unsigned gtid = blockIdx.x * 256 + threadIdx.x;
    unsigned warp = gtid >> 5;
    unsigned p = warp * 2 + (lane >> 4);       // pair served by this lane
    unsigned l16 = lane & 15;

    int c  = __ldg(central + p);
    int nb = __ldg(neigh + p);

    // gather g row (L2-resident), 4 descriptors per lane
    float4 g = *(const float4*)(g_table + (size_t)c * N_DESC + l16 * 4);

    const float* base = derivs + (size_t)p * N_DESC + l16 * 4;
    const size_t ds = (size_t)N_PAIRS * N_DESC;
    float4 v0 = __ldcs((const float4*)(base));
    float4 v1 = __ldcs((const float4*)(base + ds));
    float4 v2 = __ldcs((const float4*)(base + 2 * ds));

    float s0 = fmaf(v0.x, g.x, fmaf(v0.y, g.y, fmaf(v0.z, g.z, v0.w * g.w)));
    float s1 = fmaf(v1.x, g.x, fmaf(v1.y, g.y, fmaf(v1.z, g.z, v1.w * g.w)));
    float s2 = fmaf(v2.x, g.x, fmaf(v2.y, g.y, fmaf(v2.z, g.z, v2.w * g.w)));

    // reduce within each 16-lane half (xor offsets stay inside the half)
    #pragma unroll
    for (int o = 8; o > 0; o >>= 1) {
        s0 += __shfl_xor_sync(0xFFFFFFFFu, s0, o);
        s1 += __shfl_xor_sync(0xFFFFFFFFu, s1, o);
        s2 += __shfl_xor_sync(0xFFFFFFFFu, s2, o);
    }

    if (l16 < 3) {
        float s = (l16 == 0) ? s0 : (l16 == 1) ? s1 : s2;
        atomicAdd(out_f + (size_t)l16 * N_ATOMS + nb, -s);
    }
}

// ---------------------------------------------------------------------------
extern "C" void kernel_launch(void* const* d_in, const int* in_sizes, int n_in,
                              void* d_out, int out_size) {
    const float* coeffs   = (const float*)d_in[0];   // [1, N_ATOMS, 64]
    const float* derivs   = (const float*)d_in[1];   // [1, 3, N_PAIRS, 64]
    const float* w1       = (const float*)d_in[2];
    const float* b1       = (const float*)d_in[3];
    const float* w_last   = (const float*)d_in[4];
    const float* b_last   = (const float*)d_in[5];
    const int*   central  = (const int*)d_in[6];
    const int*   neigh    = (const int*)d_in[7];
    float* out = (float*)d_out;                      // [0]=energy, [1..30000]=forces [3,N_ATOMS]

    // 1) g table + energy partials + force zeroing (single launch)
    table_energy_kernel<<<TABLE_BLOCKS, TABLE_TPB>>>(
        (const float4*)coeffs, (const float4*)w1, (const float4*)b1,
        (const float4*)w_last, out + 1);

    // 2) pair contraction + scatter + energy finalize (non-persistent)
    {
        int warps = N_PAIRS / 2;                 // 250000, exact
        int blocks = warps / 8;                  // 31250, exact (8 warps/block)
        pair_kernel<<<blocks, 256>>>(derivs, central, neigh, b_last, out);
    }
}

// round 7
// speedup vs baseline: 1.1641x; 1.0053x over previous
#include <cuda_runtime.h>

#define N_ATOMS 10000
#define N_PAIRS 500000
#define N_DESC  64

#define TABLE_TPB 256
#define TABLE_BLOCKS ((N_ATOMS * N_DESC / 4 + TABLE_TPB - 1) / TABLE_TPB)   // 625

// Precomputed per-atom table: g[n,d] = (1 - tanh^2(coeffs*w1+b1)) * w1[d] * w_last[d]
__device__ float g_table[N_ATOMS * N_DESC];
// Per-block energy partials from the table kernel
__device__ float e_partials[TABLE_BLOCKS];

// ---------------------------------------------------------------------------
// Kernel 1: build g table (float4-vectorized), zero forces, write per-block
// energy partials. One thread per 4 (atom,descriptor) elements.
// ---------------------------------------------------------------------------
__global__ void table_energy_kernel(const float4* __restrict__ coeffs4,
                                    const float4* __restrict__ w1_4,
                                    const float4* __restrict__ b1_4,
                                    const float4* __restrict__ wl_4,
                                    float* __restrict__ out_f) {   // out+1
    int idx = blockIdx.x * blockDim.x + threadIdx.x;   // over 160000 float4s
    float e_contrib = 0.0f;
    if (idx < N_ATOMS * N_DESC / 4) {
        int d4 = idx & (N_DESC / 4 - 1);               // descriptor group 0..15
        float4 w  = w1_4[d4];
        float4 b  = b1_4[d4];
        float4 wl = wl_4[d4];
        float4 c  = coeffs4[idx];
        float ex = tanhf(fmaf(c.x, w.x, b.x));
        float ey = tanhf(fmaf(c.y, w.y, b.y));
        float ez = tanhf(fmaf(c.z, w.z, b.z));
        float ew = tanhf(fmaf(c.w, w.w, b.w));
        float4 g;
        g.x = (1.0f - ex * ex) * w.x * wl.x;
        g.y = (1.0f - ey * ey) * w.y * wl.y;
        g.z = (1.0f - ez * ez) * w.z * wl.z;
        g.w = (1.0f - ew * ew) * w.w * wl.w;
        *(float4*)(g_table + idx * 4) = g;
        e_contrib = fmaf(ex, wl.x, fmaf(ey, wl.y, fmaf(ez, wl.z, ew * wl.w)));
    }
    // zero the force output (3*N_ATOMS = 30000 floats; out_f only 4B-aligned)
    if (idx < 3 * N_ATOMS) out_f[idx] = 0.0f;

    // block reduction of energy contribution
    __shared__ float red[TABLE_TPB / 32];
    #pragma unroll
    for (int o = 16; o > 0; o >>= 1)
        e_contrib += __shfl_xor_sync(0xFFFFFFFFu, e_contrib, o);
    int lane = threadIdx.x & 31;
    int wid = threadIdx.x >> 5;
    if (lane == 0) red[wid] = e_contrib;
    __syncthreads();
    if (wid == 0) {
        float v = (lane < (TABLE_TPB >> 5)) ? red[lane] : 0.0f;
        #pragma unroll
        for (int o = 16; o > 0; o >>= 1)
            v += __shfl_xor_sync(0xFFFFFFFFu, v, o);
        if (lane == 0) e_partials[blockIdx.x] = v;
    }
}

// ---------------------------------------------------------------------------
// Kernel 2: pair contraction + scatter. Non-persistent (wall-clock best):
// TWO pairs per warp, lanes 0-15 -> pair 2w, lanes 16-31 -> pair 2w+1.
// Each lane owns 4 descriptors (float4); each deriv load is one warp-wide
// contiguous 512 B LDG.128. Derivs use __ldcs (evict-first) so L2 keeps
// g_table + the force accumulator resident.
// Block 0 / warp 0 additionally finalizes the energy from the partials.
// Grid covers exactly N_PAIRS/2 warps — no bounds check needed.
// ---------------------------------------------------------------------------
__global__ void __launch_bounds__(256) pair_kernel(
    const float* __restrict__ derivs,          // [3, N_PAIRS, 64]
    const int* __restrict__ central,
    const int* __restrict__ neigh,
    const float* __restrict__ b_last,
    float* __restrict__ out)                   // [0]=energy, [1..]=forces [3,N_ATOMS]
{
    const unsigned lane = threadIdx.x & 31;
    float* out_f = out + 1;

    // ---- energy finalize (one warp; table kernel already completed) ----
    if (blockIdx.x == 0 && (threadIdx.x >> 5) == 0) {
        float v = 0.0f;
        for (int i = lane; i < TABLE_BLOCKS; i += 32) v += e_partials[i];
        #pragma unroll
        for (int o = 16; o > 0; o >>= 1)
            v += __shfl_xor_sync(0xFFFFFFFFu, v, o);
        if (lane == 0) out[0] = v * (1.0f / (float)N_ATOMS) + b_last[0];
    }

    unsigned gtid = blockIdx.x * 256 + threadIdx.x;
    unsigned warp = gtid >> 5;
    unsigned p = warp * 2 + (lane >> 4);       // pair served by this lane
    unsigned l16 = lane & 15;

    int c  = __ldg(central + p);
    int nb = __ldg(neigh + p);

    // gather g row (L2-resident), 4 descriptors per lane
    float4 g = *(const float4*)(g_table + (size_t)c * N_DESC + l16 * 4);

    const float* base = derivs + (size_t)p * N_DESC + l16 * 4;
    const size_t ds = (size_t)N_PAIRS * N_DESC;
    float4 v0 = __ldcs((const float4*)(base));
    float4 v1 = __ldcs((const float4*)(base + ds));
    float4 v2 = __ldcs((const float4*)(base + 2 * ds));

    float s0 = fmaf(v0.x, g.x, fmaf(v0.y, g.y, fmaf(v0.z, g.z, v0.w * g.w)));
    float s1 = fmaf(v1.x, g.x, fmaf(v1.y, g.y, fmaf(v1.z, g.z, v1.w * g.w)));
    float s2 = fmaf(v2.x, g.x, fmaf(v2.y, g.y, fmaf(v2.z, g.z, v2.w * g.w)));

    // reduce within each 16-lane half (xor offsets stay inside the half)
    #pragma unroll
    for (int o = 8; o > 0; o >>= 1) {
        s0 += __shfl_xor_sync(0xFFFFFFFFu, s0, o);
        s1 += __shfl_xor_sync(0xFFFFFFFFu, s1, o);
        s2 += __shfl_xor_sync(0xFFFFFFFFu, s2, o);
    }

    if (l16 < 3) {
        float s = (l16 == 0) ? s0 : (l16 == 1) ? s1 : s2;
        atomicAdd(out_f + (size_t)l16 * N_ATOMS + nb, -s);
    }
}

// ---------------------------------------------------------------------------
extern "C" void kernel_launch(void* const* d_in, const int* in_sizes, int n_in,
                              void* d_out, int out_size) {
    const float* coeffs   = (const float*)d_in[0];   // [1, N_ATOMS, 64]
    const float* derivs   = (const float*)d_in[1];   // [1, 3, N_PAIRS, 64]
    const float* w1       = (const float*)d_in[2];
    const float* b1       = (const float*)d_in[3];
    const float* w_last   = (const float*)d_in[4];
    const float* b_last   = (const float*)d_in[5];
    const int*   central  = (const int*)d_in[6];
    const int*   neigh    = (const int*)d_in[7];
    float* out = (float*)d_out;                      // [0]=energy, [1..30000]=forces [3,N_ATOMS]

    // 1) g table + energy partials + force zeroing (single launch)
    table_energy_kernel<<<TABLE_BLOCKS, TABLE_TPB>>>(
        (const float4*)coeffs, (const float4*)w1, (const float4*)b1,
        (const float4*)w_last, out + 1);

    // 2) pair contraction + scatter + energy finalize (non-persistent)
    {
        int warps = N_PAIRS / 2;                 // 250000, exact
        int blocks = warps / 8;                  // 31250, exact (8 warps/block)
        pair_kernel<<<blocks, 256>>>(derivs, central, neigh, b_last, out);
    }
}